// round 17
// baseline (speedup 1.0000x reference)
#include <cuda_runtime.h>
#include <cstdint>

// Problem constants
#define B_SZ   1024
#define F_SZ   784
#define OUT_F  1024
#define OR_T   32
#define AND_T  16
#define NLIT   (1 + 2 * F_SZ)   // 1569 literals
#define NBG    (B_SZ / 32)      // 32 words per literal row = 128 B
#define TBL_WORDS (NLIT * NBG)  // 50208 words = 200832 B
#define TBL_BYTES (TBL_WORDS * 4)

#define GRIDX      148           // one CTA per SM, 37 clusters of 4
#define NTHREADS   512
#define CLUSTER_SZ 4
#define MAX_OPB    7             // ceil(1024/148)
#define W_MAX_WORDS (MAX_OPB * OR_T * AND_T)        // 3584 words = 14336 B
#define RES_WORDS  (MAX_OPB * 2 * NBG)              // 448 words
#define MBAR_OFF_W (TBL_WORDS + W_MAX_WORDS + RES_WORDS + 4)  // 16B-aligned pad
#define SMEM_BYTES ((MBAR_OFF_W + 4) * 4)           // ~217.0 KB

__device__ __align__(16) uint32_t g_T[TBL_WORDS];

// ---------------------------------------------------------------------------
// Pack kernel: grid (25, 32), 128 threads (~1us). Dual-polarity table.
// ---------------------------------------------------------------------------
__global__ __launch_bounds__(128) void pack_kernel(const float* __restrict__ x) {
    __shared__ float tile[32][33];

    const int ft  = blockIdx.x;
    const int bg  = blockIdx.y;
    const int tid = threadIdx.x;
    const int f0  = ft * 32;

    const int c  = tid & 31;
    const int r0 = tid >> 5;
    #pragma unroll
    for (int r = r0; r < 32; r += 4) {
        const int f = f0 + c;
        tile[r][c] = (f < F_SZ) ? x[(size_t)(bg * 32 + r) * F_SZ + f] : 0.0f;
    }
    __syncthreads();

    const int lane = tid & 31;
    const int w    = tid >> 5;
    #pragma unroll
    for (int ff = w; ff < 32; ff += 4) {
        const int f = f0 + ff;
        if (f >= F_SZ) break;
        uint32_t m = __ballot_sync(0xFFFFFFFFu, tile[lane][ff] != 0.0f);
        if (lane == 0) {
            g_T[(size_t)(1 + f) * NBG + bg]        = m;
            g_T[(size_t)(1 + F_SZ + f) * NBG + bg] = ~m;
        }
    }
    if (ft == 0 && tid == 0) g_T[bg] = 0xFFFFFFFFu;
}

// ---------------------------------------------------------------------------
// Logic kernel: 148 blocks (one per SM; 37 clusters of 4) x 512 threads.
//  - Output range per CTA: [bid*1024/148, (bid+1)*1024/148) -> 6 or 7 outputs
//    (13% less per-SM crossbar/issue work than 8, and zero idle SMs).
//  - Cluster leader multicasts the 200KB table; each CTA bulk-copies its own
//    weights on the same mbarrier.
//  - Gather: proven R9/R14 form. Warp pair per output (h = term half), lane =
//    (th = lane>>4 term-of-pair, bgp = lane&15 bg-pair), conflict-free LDS.64.
// ---------------------------------------------------------------------------
__global__ __launch_bounds__(NTHREADS, 1) __cluster_dims__(CLUSTER_SZ, 1, 1)
void logic_kernel(const int* __restrict__ weights, float* __restrict__ out) {

    extern __shared__ uint32_t smem[];
    uint32_t* sT   = smem;                     // table (50208 words)
    uint32_t* sw   = smem + TBL_WORDS;         // weights (<= 3584 words)
    uint32_t* resb = sw + W_MAX_WORDS;         // results (<= 448 words)
    uint32_t  mbar_addr;
    {
        uint64_t* mb64 = (uint64_t*)(smem + MBAR_OFF_W);
        asm("{ .reg .u64 t; cvta.to.shared.u64 t, %1; cvt.u32.u64 %0, t; }"
            : "=r"(mbar_addr) : "l"((void*)mb64));
    }

    const int tid    = threadIdx.x;
    const int bid    = blockIdx.x;
    const int oStart = (bid * OUT_F) / GRIDX;
    const int oEnd   = ((bid + 1) * OUT_F) / GRIDX;
    const int cnt    = oEnd - oStart;          // 6 or 7
    const uint32_t wBytes = (uint32_t)(cnt * OR_T * AND_T * 4);   // mult of 16

    uint32_t rank;
    asm("mov.u32 %0, %%cluster_ctarank;" : "=r"(rank));

    if (tid == 0) {
        asm volatile("mbarrier.init.shared.b64 [%0], 1;" :: "r"(mbar_addr) : "memory");
    }
    __syncthreads();
    if (tid == 0) {
        asm volatile("mbarrier.arrive.expect_tx.shared.b64 _, [%0], %1;"
                     :: "r"(mbar_addr),
                        "r"((uint32_t)TBL_BYTES + wBytes) : "memory");
    }
    // All cluster mbarriers initialized + expecting before multicast lands
    asm volatile("barrier.cluster.arrive.aligned;" ::: "memory");
    asm volatile("barrier.cluster.wait.aligned;"   ::: "memory");

    if (tid == 0) {
        uint32_t sdst;
        asm("{ .reg .u64 t; cvta.to.shared.u64 t, %1; cvt.u32.u64 %0, t; }"
            : "=r"(sdst) : "l"((void*)sT));

        if (rank == 0) {
            // Leader: multicast table to all 4 cluster CTAs (8 x 25104B)
            const char* gsrc = (const char*)g_T;
            const uint32_t chunk = TBL_BYTES / 8;      // 25104 = 16*1569
            #pragma unroll
            for (int i = 0; i < 8; ++i) {
                asm volatile(
                    "cp.async.bulk.shared::cluster.global.mbarrier::complete_tx::bytes"
                    ".multicast::cluster [%0], [%1], %2, [%3], %4;"
                    :: "r"(sdst + i * chunk), "l"(gsrc + (size_t)i * chunk),
                       "r"(chunk), "r"(mbar_addr),
                       "h"((uint16_t)((1u << CLUSTER_SZ) - 1u)) : "memory");
            }
        }
        // Every CTA: its own weights (cnt * 2048 B)
        {
            const char* wsrc = (const char*)(weights + (size_t)oStart * OR_T * AND_T);
            asm volatile(
                "cp.async.bulk.shared::cta.global.mbarrier::complete_tx::bytes "
                "[%0], [%1], %2, [%3];"
                :: "r"(sdst + (uint32_t)TBL_BYTES), "l"(wsrc),
                   "r"(wBytes), "r"(mbar_addr) : "memory");
        }
    }
    __syncthreads();

    // Wait for table + weights
    {
        uint32_t done;
        asm volatile(
            "{\n\t.reg .pred p;\n\t"
            "mbarrier.try_wait.parity.acquire.cta.shared::cta.b64 p, [%1], 0;\n\t"
            "selp.b32 %0, 1, 0, p;\n\t}"
            : "=r"(done) : "r"(mbar_addr) : "memory");
        if (!done) {
            asm volatile(
                "{\n\t.reg .pred P1;\n\t"
                "WL_%=:\n\t"
                "mbarrier.try_wait.parity.acquire.cta.shared::cta.b64 P1, [%0], 0, 0x989680;\n\t"
                "@P1 bra.uni WD_%=;\n\t"
                "bra.uni WL_%=;\n\t"
                "WD_%=:\n\t}"
                :: "r"(mbar_addr) : "memory");
        }
    }

    const int wid  = tid >> 5;                 // 0..15
    const int lane = tid & 31;
    const int o    = wid >> 1;                 // output slot (0..7)
    const int h    = wid & 1;                  // term half
    const int th   = lane >> 4;                // term selector within pass
    const int bgp  = lane & 15;                // batch-group pair (uint2)

    if (o < cnt) {
        const uint32_t* swb = sw + o * (OR_T * AND_T);
        const uint2*    sT2 = (const uint2*)sT;

        uint2 res = make_uint2(0u, 0u);
        #pragma unroll
        for (int t2 = 0; t2 < 8; ++t2) {
            const int t = h * 16 + t2 * 2 + th;         // this lane's term
            const uint4* tw4 = (const uint4*)(swb + t * AND_T);
            uint2 m0 = make_uint2(~0u, ~0u), m1 = make_uint2(~0u, ~0u);
            uint32_t orw = 0;
            #pragma unroll
            for (int k4 = 0; k4 < 4; ++k4) {
                const uint4 w4 = tw4[k4];               // broadcast LDS.128
                orw |= (w4.x | w4.y | w4.z | w4.w);
                const uint2 a = sT2[w4.x * 16 + bgp];   // LDS.64 gathers
                const uint2 b = sT2[w4.y * 16 + bgp];
                const uint2 c = sT2[w4.z * 16 + bgp];
                const uint2 d = sT2[w4.w * 16 + bgp];
                m0.x &= a.x & c.x;  m0.y &= a.y & c.y;
                m1.x &= b.x & d.x;  m1.y &= b.y & d.y;
            }
            const uint32_t sel = (orw != 0) ? ~0u : 0u; // all-zero term masked
            res.x |= m0.x & m1.x & sel;
            res.y |= m0.y & m1.y & sel;
        }
        // OR across th (lanes l <-> l+16 share bgp)
        res.x |= __shfl_xor_sync(0xFFFFFFFFu, res.x, 16);
        res.y |= __shfl_xor_sync(0xFFFFFFFFu, res.y, 16);

        if (lane < 16) {
            resb[(o * 2 + h) * NBG + bgp * 2]     = res.x;
            resb[(o * 2 + h) * NBG + bgp * 2 + 1] = res.y;
        }
    }
    __syncthreads();

    // Store: thread b handles batches b, b+512; cnt scalar floats each
    // (<= 28B contiguous per thread -> sector-efficient; output is 4MB total)
    #pragma unroll
    for (int b = tid; b < B_SZ; b += NTHREADS) {        // 2 iterations
        const int bg = b >> 5;
        const int j  = b & 31;
        float* dst = out + (size_t)b * OUT_F + oStart;
        #pragma unroll
        for (int ow = 0; ow < MAX_OPB; ++ow) {
            if (ow < cnt) {
                const uint32_t r = resb[(ow * 2 + 0) * NBG + bg] |
                                   resb[(ow * 2 + 1) * NBG + bg];
                dst[ow] = (float)((r >> j) & 1u);
            }
        }
    }
}

// ---------------------------------------------------------------------------
extern "C" void kernel_launch(void* const* d_in, const int* in_sizes, int n_in,
                              void* d_out, int out_size) {
    const float* x       = (const float*)d_in[0];   // (1024, 784) float32
    const int*   weights = (const int*)d_in[1];     // (1024, 32, 16) int32
    float*       out     = (float*)d_out;           // (1024, 1024) float32

    cudaFuncSetAttribute(logic_kernel,
                         cudaFuncAttributeMaxDynamicSharedMemorySize, SMEM_BYTES);

    dim3 pgrid(25, 32);
    pack_kernel<<<pgrid, 128>>>(x);
    logic_kernel<<<GRIDX, NTHREADS, SMEM_BYTES>>>(weights, out);
}